// round 7
// baseline (speedup 1.0000x reference)
#include <cuda_runtime.h>
#include <math.h>

typedef unsigned long long u64;

__device__ __forceinline__ void ffma2(u64 &d, u64 a, u64 b) {
    asm("fma.rn.f32x2 %0, %1, %2, %0;" : "+l"(d) : "l"(a), "l"(b));
}
__device__ __forceinline__ void unpack2(u64 v, float &lo, float &hi) {
    asm("mov.b64 {%0, %1}, %2;" : "=f"(lo), "=f"(hi) : "l"(v));
}

#define BHX 32
#define SEQ 2048
#define HD  64
#define FEAT_ELEMS (BHX*SEQ*HD)

__device__ __align__(128) float g_qf[FEAT_ELEMS];
__device__ __align__(128) float g_kf[FEAT_ELEMS];
__device__ __align__(128) float g_rq[FEAT_ELEMS];
__device__ __align__(128) float g_rk[FEAT_ELEMS];
__device__ __align__(128) float g_v [FEAT_ELEMS];
__device__ __align__(128) float g_ao[FEAT_ELEMS];

// ---------------------------------------------------------------------------
// Kernel 1: QKV GEMM + bias + elu+1 + RoPE. Double-buffered smem, A stored
// as duplicated (a,a) float2 pairs so FFMA2 A-operand is a raw LDS.64.
// smem: As2 [2][16][130] float2 (33280 B) + Bs [2][16][128] float (16384 B).
// ---------------------------------------------------------------------------
__global__ __launch_bounds__(256, 2) void qkv_gemm(const float* __restrict__ X,
                                                   const float* __restrict__ W,
                                                   const float* __restrict__ bias) {
    extern __shared__ char qsm[];
    float2* As2 = (float2*)qsm;                 // [(buf*16+k)*130 + row]
    float*  Bsf = (float*)(qsm + 33280);        // [(buf*16+k)*128 + col]
    const int tid = threadIdx.x;
    const int bm = blockIdx.y * 128;
    const int bn = blockIdx.x * 128;
    const int tx = tid & 15, ty = tid >> 4;
    const int ar = tid >> 2,  ac = (tid & 3) * 4;
    const int br = tid >> 5,  bc = (tid & 31) * 4;

    u64 acc2[8][4];
    #pragma unroll
    for (int i = 0; i < 8; i++)
        #pragma unroll
        for (int p = 0; p < 4; p++) acc2[i][p] = 0ull;

    float4 rA[2], rB[2];
    // prologue: tile 0
    #pragma unroll
    for (int l = 0; l < 2; l++)
        rA[l] = *(const float4*)(X + (size_t)(bm + ar + 64*l) * 1024 + 0 + ac);
    #pragma unroll
    for (int l = 0; l < 2; l++)
        rB[l] = *(const float4*)(W + (size_t)(0 + br + 8*l) * 3072 + bn + bc);
    #pragma unroll
    for (int l = 0; l < 2; l++) {
        int r = ar + 64*l;
        As2[(ac+0)*130 + r] = make_float2(rA[l].x, rA[l].x);
        As2[(ac+1)*130 + r] = make_float2(rA[l].y, rA[l].y);
        As2[(ac+2)*130 + r] = make_float2(rA[l].z, rA[l].z);
        As2[(ac+3)*130 + r] = make_float2(rA[l].w, rA[l].w);
    }
    #pragma unroll
    for (int l = 0; l < 2; l++)
        *(float4*)(&Bsf[(br + 8*l)*128 + bc]) = rB[l];
    __syncthreads();

    for (int kt = 0; kt < 64; kt++) {
        const int buf = kt & 1;
        if (kt < 63) {
            int k0 = (kt + 1) * 16;
            #pragma unroll
            for (int l = 0; l < 2; l++)
                rA[l] = *(const float4*)(X + (size_t)(bm + ar + 64*l) * 1024 + k0 + ac);
            #pragma unroll
            for (int l = 0; l < 2; l++)
                rB[l] = *(const float4*)(W + (size_t)(k0 + br + 8*l) * 3072 + bn + bc);
        }
        #pragma unroll
        for (int k = 0; k < 16; k++) {
            u64 a2[8];
            #pragma unroll
            for (int i = 0; i < 8; i++)
                a2[i] = *(const u64*)(As2 + (buf*16 + k)*130 + ty*8 + i);
            const u64* brow = (const u64*)(Bsf + (buf*16 + k)*128 + tx*8);
            u64 b0 = brow[0], b1 = brow[1], b2 = brow[2], b3 = brow[3];
            #pragma unroll
            for (int i = 0; i < 8; i++) {
                ffma2(acc2[i][0], a2[i], b0);
                ffma2(acc2[i][1], a2[i], b1);
                ffma2(acc2[i][2], a2[i], b2);
                ffma2(acc2[i][3], a2[i], b3);
            }
        }
        if (kt < 63) {
            const int nb = buf ^ 1;
            #pragma unroll
            for (int l = 0; l < 2; l++) {
                int r = ar + 64*l;
                As2[(nb*16 + ac+0)*130 + r] = make_float2(rA[l].x, rA[l].x);
                As2[(nb*16 + ac+1)*130 + r] = make_float2(rA[l].y, rA[l].y);
                As2[(nb*16 + ac+2)*130 + r] = make_float2(rA[l].z, rA[l].z);
                As2[(nb*16 + ac+3)*130 + r] = make_float2(rA[l].w, rA[l].w);
            }
            #pragma unroll
            for (int l = 0; l < 2; l++)
                *(float4*)(&Bsf[(nb*16 + br + 8*l)*128 + bc]) = rB[l];
        }
        __syncthreads();
    }

    // Epilogue: bias, elu+1, RoPE, head-scatter.
    const int col_base = bn + tx * 8;
    const int which = col_base >> 10;
    float theta[4];
    if (which != 2) {
        #pragma unroll
        for (int p = 0; p < 4; p++) {
            int pi = ((col_base & 63) + 2*p) >> 1;
            theta[p] = (float)(1.0 / pow(10000.0, (double)pi * (1.0 / 32.0)));
        }
    }
    #pragma unroll
    for (int i = 0; i < 8; i++) {
        int r = bm + ty * 8 + i;
        int b = r >> 11, n = r & 2047;
        #pragma unroll
        for (int p = 0; p < 4; p++) {
            int col0 = col_base + 2 * p;
            int d0 = col0 & 1023;
            int h = d0 >> 6, e0 = d0 & 63;
            int idx0 = ((b * 16 + h) * 2048 + n) * 64 + e0;
            float a0, a1;
            unpack2(acc2[i][p], a0, a1);
            float v0 = a0 + bias[col0];
            float v1 = a1 + bias[col0 + 1];
            if (which == 2) {
                g_v[idx0]     = v0;
                g_v[idx0 + 1] = v1;
            } else {
                float f0 = (v0 > 0.f) ? (v0 + 1.f) : expf(v0);
                float f1 = (v1 > 0.f) ? (v1 + 1.f) : expf(v1);
                float s, c;
                sincosf((float)n * theta[p], &s, &c);
                float r0 = f0 * c - f1 * s;
                float r1 = f0 * s + f1 * c;
                if (which == 0) {
                    g_qf[idx0] = f0; g_qf[idx0 + 1] = f1;
                    g_rq[idx0] = r0; g_rq[idx0 + 1] = r1;
                } else {
                    g_kf[idx0] = f0; g_kf[idx0 + 1] = f1;
                    g_rk[idx0] = r0; g_rk[idx0 + 1] = r1;
                }
            }
        }
    }
}

// ---------------------------------------------------------------------------
// Kernel 2: fused attention, (num,den)-paired FFMA2, K/V register prefetch.
// smem: qp [64][66] f2 | kp [64][66] f2 (w2 [64][65] f2 aliases kp) | v_s [64][64] f.
// Total 83968 B -> 2 CTAs/SM.
// ---------------------------------------------------------------------------
#define SQ2 66

__global__ __launch_bounds__(256, 2) void attn_kernel() {
    extern __shared__ char smraw[];
    float2* qp  = (float2*)smraw;                  // 33792 B
    float2* kp  = (float2*)(smraw + 33792);        // 33792 B
    float2* w2  = (float2*)(smraw + 33792);        // alias kp: [j*65+i], 33280 B
    float*  v_s = (float*)(smraw + 67584);         // 16384 B
    const int tid = threadIdx.x;
    const int tx = tid & 15, ty = tid >> 4;
    const int bh = blockIdx.y;
    const int q0 = blockIdx.x * 64;
    const size_t qbase = (size_t)(bh * 2048 + q0) * 64;
    const size_t kbase0 = (size_t)(bh * 2048) * 64;

    // Q tiles -> qp (interleaved (rq, qf))
    #pragma unroll
    for (int l = 0; l < 4; l++) {
        int t = tid + l * 256;
        int row = t >> 4, c4 = (t & 15) * 4;
        float4 a = *(const float4*)(g_rq + qbase + row * 64 + c4);
        float4 b = *(const float4*)(g_qf + qbase + row * 64 + c4);
        qp[(c4+0)*SQ2 + row] = make_float2(a.x, b.x);
        qp[(c4+1)*SQ2 + row] = make_float2(a.y, b.y);
        qp[(c4+2)*SQ2 + row] = make_float2(a.z, b.z);
        qp[(c4+3)*SQ2 + row] = make_float2(a.w, b.w);
    }

    // prefetch K/V tile 0 into registers
    float4 ka[4], kb[4], vr[4];
    {
        const size_t kb0 = kbase0;
        #pragma unroll
        for (int l = 0; l < 4; l++) {
            int t = tid + l * 256;
            int row = t >> 4, c4 = (t & 15) * 4;
            ka[l] = *(const float4*)(g_rk + kb0 + row * 64 + c4);
            kb[l] = *(const float4*)(g_kf + kb0 + row * 64 + c4);
            vr[l] = *(const float4*)(g_v  + kb0 + row * 64 + c4);
        }
    }

    u64 outp[8];
    #pragma unroll
    for (int i = 0; i < 8; i++) outp[i] = 0ull;

    __syncthreads();   // qp visible

    for (int kt = 0; kt < 32; kt++) {
        // store prefetched K/V tiles
        #pragma unroll
        for (int l = 0; l < 4; l++) {
            int t = tid + l * 256;
            int row = t >> 4, c4 = (t & 15) * 4;
            kp[(c4+0)*SQ2 + row] = make_float2(ka[l].x, kb[l].x);
            kp[(c4+1)*SQ2 + row] = make_float2(ka[l].y, kb[l].y);
            kp[(c4+2)*SQ2 + row] = make_float2(ka[l].z, kb[l].z);
            kp[(c4+3)*SQ2 + row] = make_float2(ka[l].w, kb[l].w);
            *(float4*)(v_s + row * 64 + c4) = vr[l];
        }
        __syncthreads();

        // num/den paired GEMM
        u64 acc2[16];
        #pragma unroll
        for (int i = 0; i < 16; i++) acc2[i] = 0ull;
        #pragma unroll 4
        for (int k = 0; k < 64; k++) {
            u64 a[4], b[4];
            #pragma unroll
            for (int r = 0; r < 4; r++)
                a[r] = *(const u64*)(qp + k*SQ2 + ty + 16*r);
            #pragma unroll
            for (int c = 0; c < 4; c++)
                b[c] = *(const u64*)(kp + k*SQ2 + tx + 16*c);
            #pragma unroll
            for (int r = 0; r < 4; r++)
                #pragma unroll
                for (int c = 0; c < 4; c++)
                    ffma2(acc2[r*4+c], a[r], b[c]);
        }

        // prefetch next K/V tile (hidden under w@v below)
        if (kt < 31) {
            const size_t kbn = kbase0 + (size_t)(kt + 1) * 64 * 64;
            #pragma unroll
            for (int l = 0; l < 4; l++) {
                int t = tid + l * 256;
                int row = t >> 4, c4 = (t & 15) * 4;
                ka[l] = *(const float4*)(g_rk + kbn + row * 64 + c4);
                kb[l] = *(const float4*)(g_kf + kbn + row * 64 + c4);
                vr[l] = *(const float4*)(g_v  + kbn + row * 64 + c4);
            }
        }
        __syncthreads();   // kp reads done -> w2 may overwrite

        // w = num/den, stored as duplicated pairs (w,w), j-major
        #pragma unroll
        for (int r = 0; r < 4; r++)
            #pragma unroll
            for (int c = 0; c < 4; c++) {
                float nu, de;
                unpack2(acc2[r*4+c], nu, de);
                float wv = __fdividef(nu, de);
                w2[(tx + 16*c) * 65 + ty + 16*r] = make_float2(wv, wv);
            }
        __syncthreads();   // w2 visible

        // out += w @ v
        #pragma unroll 4
        for (int j = 0; j < 64; j++) {
            u64 wp[4];
            #pragma unroll
            for (int r = 0; r < 4; r++)
                wp[r] = *(const u64*)(w2 + j*65 + ty + 16*r);
            u64 v0 = *(const u64*)(v_s + j*64 + 2*tx);
            u64 v1 = *(const u64*)(v_s + j*64 + 2*tx + 32);
            #pragma unroll
            for (int r = 0; r < 4; r++) {
                ffma2(outp[r*2],   wp[r], v0);
                ffma2(outp[r*2+1], wp[r], v1);
            }
        }
        __syncthreads();   // w@v done -> next iter may overwrite kp/w2/v_s
    }

    float* og = g_ao + qbase;
    #pragma unroll
    for (int r = 0; r < 4; r++) {
        int row = ty + 16*r;
        float lo, hi;
        unpack2(outp[r*2], lo, hi);
        *(float2*)(og + row*64 + 2*tx) = make_float2(lo, hi);
        unpack2(outp[r*2+1], lo, hi);
        *(float2*)(og + row*64 + 2*tx + 32) = make_float2(lo, hi);
    }
}

// ---------------------------------------------------------------------------
// Kernel 3: output projection (head-gathered A), double-buffered + paired A.
// ---------------------------------------------------------------------------
__global__ __launch_bounds__(256, 2) void proj_gemm(const float* __restrict__ W,
                                                    const float* __restrict__ bias,
                                                    float* __restrict__ out) {
    extern __shared__ char psm[];
    float2* As2 = (float2*)psm;
    float*  Bsf = (float*)(psm + 33280);
    const int tid = threadIdx.x;
    const int bm = blockIdx.y * 128;
    const int bn = blockIdx.x * 128;
    const int tx = tid & 15, ty = tid >> 4;
    const int ar = tid >> 2,  ac = (tid & 3) * 4;
    const int br = tid >> 5,  bc = (tid & 31) * 4;

    u64 acc2[8][4];
    #pragma unroll
    for (int i = 0; i < 8; i++)
        #pragma unroll
        for (int p = 0; p < 4; p++) acc2[i][p] = 0ull;

    float4 rA[2], rB[2];
    auto loadA = [&](int k0, int l) -> float4 {
        int r = bm + ar + 64*l;
        int d = k0 + ac;
        int b = r >> 11, n = r & 2047;
        int h = d >> 6,  e = d & 63;
        return *(const float4*)(g_ao + (size_t)((b * 16 + h) * 2048 + n) * 64 + e);
    };

    #pragma unroll
    for (int l = 0; l < 2; l++) rA[l] = loadA(0, l);
    #pragma unroll
    for (int l = 0; l < 2; l++)
        rB[l] = *(const float4*)(W + (size_t)(0 + br + 8*l) * 1024 + bn + bc);
    #pragma unroll
    for (int l = 0; l < 2; l++) {
        int r = ar + 64*l;
        As2[(ac+0)*130 + r] = make_float2(rA[l].x, rA[l].x);
        As2[(ac+1)*130 + r] = make_float2(rA[l].y, rA[l].y);
        As2[(ac+2)*130 + r] = make_float2(rA[l].z, rA[l].z);
        As2[(ac+3)*130 + r] = make_float2(rA[l].w, rA[l].w);
    }
    #pragma unroll
    for (int l = 0; l < 2; l++)
        *(float4*)(&Bsf[(br + 8*l)*128 + bc]) = rB[l];
    __syncthreads();

    for (int kt = 0; kt < 64; kt++) {
        const int buf = kt & 1;
        if (kt < 63) {
            int k0 = (kt + 1) * 16;
            #pragma unroll
            for (int l = 0; l < 2; l++) rA[l] = loadA(k0, l);
            #pragma unroll
            for (int l = 0; l < 2; l++)
                rB[l] = *(const float4*)(W + (size_t)(k0 + br + 8*l) * 1024 + bn + bc);
        }
        #pragma unroll
        for (int k = 0; k < 16; k++) {
            u64 a2[8];
            #pragma unroll
            for (int i = 0; i < 8; i++)
                a2[i] = *(const u64*)(As2 + (buf*16 + k)*130 + ty*8 + i);
            const u64* brow = (const u64*)(Bsf + (buf*16 + k)*128 + tx*8);
            u64 b0 = brow[0], b1 = brow[1], b2 = brow[2], b3 = brow[3];
            #pragma unroll
            for (int i = 0; i < 8; i++) {
                ffma2(acc2[i][0], a2[i], b0);
                ffma2(acc2[i][1], a2[i], b1);
                ffma2(acc2[i][2], a2[i], b2);
                ffma2(acc2[i][3], a2[i], b3);
            }
        }
        if (kt < 63) {
            const int nb = buf ^ 1;
            #pragma unroll
            for (int l = 0; l < 2; l++) {
                int r = ar + 64*l;
                As2[(nb*16 + ac+0)*130 + r] = make_float2(rA[l].x, rA[l].x);
                As2[(nb*16 + ac+1)*130 + r] = make_float2(rA[l].y, rA[l].y);
                As2[(nb*16 + ac+2)*130 + r] = make_float2(rA[l].z, rA[l].z);
                As2[(nb*16 + ac+3)*130 + r] = make_float2(rA[l].w, rA[l].w);
            }
            #pragma unroll
            for (int l = 0; l < 2; l++)
                *(float4*)(&Bsf[(nb*16 + br + 8*l)*128 + bc]) = rB[l];
        }
        __syncthreads();
    }

    #pragma unroll
    for (int i = 0; i < 8; i++) {
        int r = bm + ty * 8 + i;
        #pragma unroll
        for (int p = 0; p < 4; p++) {
            int col0 = bn + tx * 8 + 2*p;
            float a0, a1;
            unpack2(acc2[i][p], a0, a1);
            *(float2*)(out + (size_t)r * 1024 + col0) =
                make_float2(a0 + bias[col0], a1 + bias[col0 + 1]);
        }
    }
}

// ---------------------------------------------------------------------------
extern "C" void kernel_launch(void* const* d_in, const int* in_sizes, int n_in,
                              void* d_out, int out_size) {
    const float* x     = (const float*)d_in[0];
    const float* w_qkv = (const float*)d_in[1];
    const float* b_qkv = (const float*)d_in[2];
    const float* w_out = (const float*)d_in[3];
    const float* b_out = (const float*)d_in[4];
    float* out = (float*)d_out;

    const int GEMM_SMEM = 33280 + 16384;   // 49,664 B
    const int ATTN_SMEM = 83968;
    cudaFuncSetAttribute(qkv_gemm,  cudaFuncAttributeMaxDynamicSharedMemorySize, GEMM_SMEM);
    cudaFuncSetAttribute(attn_kernel, cudaFuncAttributeMaxDynamicSharedMemorySize, ATTN_SMEM);
    cudaFuncSetAttribute(proj_gemm, cudaFuncAttributeMaxDynamicSharedMemorySize, GEMM_SMEM);

    qkv_gemm<<<dim3(24, 32), 256, GEMM_SMEM>>>(x, w_qkv, b_qkv);
    attn_kernel<<<dim3(32, 32), 256, ATTN_SMEM>>>();
    proj_gemm<<<dim3(8, 32), 256, GEMM_SMEM>>>(w_out, b_out, out);
}

// round 11
// speedup vs baseline: 1.1375x; 1.1375x over previous
#include <cuda_runtime.h>
#include <math.h>

typedef unsigned long long u64;

__device__ __forceinline__ void ffma2(u64 &d, u64 a, u64 b) {
    asm("fma.rn.f32x2 %0, %1, %2, %0;" : "+l"(d) : "l"(a), "l"(b));
}
__device__ __forceinline__ u64 pack2(float lo, float hi) {
    u64 r; asm("mov.b64 %0, {%1, %2};" : "=l"(r) : "f"(lo), "f"(hi)); return r;
}
__device__ __forceinline__ void unpack2(u64 v, float &lo, float &hi) {
    asm("mov.b64 {%0, %1}, %2;" : "=f"(lo), "=f"(hi) : "l"(v));
}

#define BHX 32
#define SEQ 2048
#define HD  64
#define FEAT_ELEMS (BHX*SEQ*HD)

__device__ __align__(128) float g_qf[FEAT_ELEMS];
__device__ __align__(128) float g_kf[FEAT_ELEMS];
__device__ __align__(128) float g_rq[FEAT_ELEMS];
__device__ __align__(128) float g_rk[FEAT_ELEMS];
__device__ __align__(128) float g_v [FEAT_ELEMS];
__device__ __align__(128) float g_ao[FEAT_ELEMS];

// ---------------------------------------------------------------------------
// Kernel 1: QKV GEMM + bias + elu+1 + RoPE (R5 config — measured 664us).
// ---------------------------------------------------------------------------
__global__ __launch_bounds__(256) void qkv_gemm(const float* __restrict__ X,
                                                const float* __restrict__ W,
                                                const float* __restrict__ bias) {
    __shared__ __align__(16) float As[16][132];
    __shared__ __align__(16) float Bs[16][128];
    const int tid = threadIdx.x;
    const int bm = blockIdx.y * 128;
    const int bn = blockIdx.x * 128;
    const int tx = tid & 15, ty = tid >> 4;
    const int ar = tid >> 2,  ac = (tid & 3) * 4;
    const int br = tid >> 5,  bc = (tid & 31) * 4;

    u64 acc2[8][4];
    #pragma unroll
    for (int i = 0; i < 8; i++)
        #pragma unroll
        for (int p = 0; p < 4; p++) acc2[i][p] = 0ull;

    for (int kt = 0; kt < 1024; kt += 16) {
        #pragma unroll
        for (int l = 0; l < 2; l++) {
            int r = ar + l * 64;
            float4 v = *(const float4*)(X + (size_t)(bm + r) * 1024 + kt + ac);
            As[ac+0][r] = v.x; As[ac+1][r] = v.y; As[ac+2][r] = v.z; As[ac+3][r] = v.w;
        }
        #pragma unroll
        for (int l = 0; l < 2; l++) {
            int r = br + l * 8;
            *(float4*)(&Bs[r][bc]) = *(const float4*)(W + (size_t)(kt + r) * 3072 + bn + bc);
        }
        __syncthreads();
        #pragma unroll
        for (int k = 0; k < 16; k++) {
            float af[8];
            *(float4*)(af)     = *(const float4*)(&As[k][ty*8]);
            *(float4*)(af + 4) = *(const float4*)(&As[k][ty*8 + 4]);
            const u64* brow = (const u64*)(&Bs[k][tx*8]);
            u64 b0 = brow[0], b1 = brow[1], b2 = brow[2], b3 = brow[3];
            #pragma unroll
            for (int i = 0; i < 8; i++) {
                u64 ap = pack2(af[i], af[i]);
                ffma2(acc2[i][0], ap, b0);
                ffma2(acc2[i][1], ap, b1);
                ffma2(acc2[i][2], ap, b2);
                ffma2(acc2[i][3], ap, b3);
            }
        }
        __syncthreads();
    }

    const int col_base = bn + tx * 8;
    const int which = col_base >> 10;
    float theta[4];
    if (which != 2) {
        #pragma unroll
        for (int p = 0; p < 4; p++) {
            int pi = ((col_base & 63) + 2*p) >> 1;
            theta[p] = (float)(1.0 / pow(10000.0, (double)pi * (1.0 / 32.0)));
        }
    }
    #pragma unroll
    for (int i = 0; i < 8; i++) {
        int r = bm + ty * 8 + i;
        int b = r >> 11, n = r & 2047;
        #pragma unroll
        for (int p = 0; p < 4; p++) {
            int col0 = col_base + 2 * p;
            int d0 = col0 & 1023;
            int h = d0 >> 6, e0 = d0 & 63;
            int idx0 = ((b * 16 + h) * 2048 + n) * 64 + e0;
            float a0, a1;
            unpack2(acc2[i][p], a0, a1);
            float v0 = a0 + bias[col0];
            float v1 = a1 + bias[col0 + 1];
            if (which == 2) {
                g_v[idx0]     = v0;
                g_v[idx0 + 1] = v1;
            } else {
                float f0 = (v0 > 0.f) ? (v0 + 1.f) : expf(v0);
                float f1 = (v1 > 0.f) ? (v1 + 1.f) : expf(v1);
                float s, c;
                sincosf((float)n * theta[p], &s, &c);
                float r0 = f0 * c - f1 * s;
                float r1 = f0 * s + f1 * c;
                if (which == 0) {
                    g_qf[idx0] = f0; g_qf[idx0 + 1] = f1;
                    g_rq[idx0] = r0; g_rq[idx0 + 1] = r1;
                } else {
                    g_kf[idx0] = f0; g_kf[idx0 + 1] = f1;
                    g_rk[idx0] = r0; g_rk[idx0 + 1] = r1;
                }
            }
        }
    }
}

// ---------------------------------------------------------------------------
// Kernel 2: fused attention, q-tile 128 x key-tile 64, 8x4 microtile.
// Thread (tx,ty): rows ty*8..ty*8+7, cols tx+16c. (num,den) paired FFMA2.
// w@v: out pairs over adjacent rows -> w operand is natural LDS.64 pair,
// v duplicated in-register (alu movs, free pipe).
// smem: qp f2[64][130] | kp f2[64][66] (w float[64][130] alias) | v f[64][68].
// Total 117760 B -> 1 CTA/SM.
// ---------------------------------------------------------------------------
#define ST_QP 130
#define ST_KP 66
#define ST_W  130
#define ST_V  68

__global__ __launch_bounds__(256) void attn_kernel() {
    extern __shared__ char smraw[];
    float2* qp  = (float2*)smraw;                   // 66560 B
    float2* kp  = (float2*)(smraw + 66560);         // 33792 B
    float*  w_s = (float*)(smraw + 66560);          // alias kp: [j*130+i], 33280 B
    float*  v_s = (float*)(smraw + 100352);         // 17408 B
    const int tid = threadIdx.x;
    const int tx = tid & 15, ty = tid >> 4;
    const int bh = blockIdx.y;
    const int q0 = blockIdx.x * 128;
    const size_t qbase = (size_t)(bh * 2048 + q0) * 64;
    const size_t kbase0 = (size_t)(bh * 2048) * 64;

    // Q tiles: 128 rows, interleaved (rq, qf) pairs, e-major
    #pragma unroll
    for (int l = 0; l < 8; l++) {
        int t = tid + l * 256;
        int row = t >> 4, c4 = (t & 15) * 4;
        float4 a = *(const float4*)(g_rq + qbase + row * 64 + c4);
        float4 b = *(const float4*)(g_qf + qbase + row * 64 + c4);
        qp[(c4+0)*ST_QP + row] = make_float2(a.x, b.x);
        qp[(c4+1)*ST_QP + row] = make_float2(a.y, b.y);
        qp[(c4+2)*ST_QP + row] = make_float2(a.z, b.z);
        qp[(c4+3)*ST_QP + row] = make_float2(a.w, b.w);
    }

    u64 out2[4][4];   // [row-pair p][e-col ce]: (out[2p][e], out[2p+1][e])
    #pragma unroll
    for (int p = 0; p < 4; p++)
        #pragma unroll
        for (int c = 0; c < 4; c++) out2[p][c] = 0ull;

    __syncthreads();

    for (int kt = 0; kt < 32; kt++) {
        const size_t kb = kbase0 + (size_t)kt * 64 * 64;
        // K tile (interleaved) + V tile
        #pragma unroll
        for (int l = 0; l < 4; l++) {
            int t = tid + l * 256;
            int row = t >> 4, c4 = (t & 15) * 4;
            float4 a = *(const float4*)(g_rk + kb + row * 64 + c4);
            float4 b = *(const float4*)(g_kf + kb + row * 64 + c4);
            kp[(c4+0)*ST_KP + row] = make_float2(a.x, b.x);
            kp[(c4+1)*ST_KP + row] = make_float2(a.y, b.y);
            kp[(c4+2)*ST_KP + row] = make_float2(a.z, b.z);
            kp[(c4+3)*ST_KP + row] = make_float2(a.w, b.w);
            *(float4*)(v_s + row * ST_V + c4) = *(const float4*)(g_v + kb + row * 64 + c4);
        }
        __syncthreads();

        // num/den: acc2[rr][c] over rows ty*8+rr, cols tx+16c
        u64 acc2[8][4];
        #pragma unroll
        for (int i = 0; i < 8; i++)
            #pragma unroll
            for (int c = 0; c < 4; c++) acc2[i][c] = 0ull;
        #pragma unroll 4
        for (int k = 0; k < 64; k++) {
            u64 a[8], b[4];
            #pragma unroll
            for (int rr = 0; rr < 8; rr++)
                a[rr] = *(const u64*)(qp + k*ST_QP + ty*8 + rr);
            #pragma unroll
            for (int c = 0; c < 4; c++)
                b[c] = *(const u64*)(kp + k*ST_KP + tx + 16*c);
            #pragma unroll
            for (int rr = 0; rr < 8; rr++)
                #pragma unroll
                for (int c = 0; c < 4; c++)
                    ffma2(acc2[rr][c], a[rr], b[c]);
        }
        __syncthreads();   // kp reads done -> w_s may overwrite

        // w = num/den, stored [j][i] as STS.64 row-pairs (conflict-free, stride 130)
        #pragma unroll
        for (int c = 0; c < 4; c++)
            #pragma unroll
            for (int p = 0; p < 4; p++) {
                float n0, d0, n1, d1;
                unpack2(acc2[2*p][c],   n0, d0);
                unpack2(acc2[2*p+1][c], n1, d1);
                u64 wpair = pack2(__fdividef(n0, d0), __fdividef(n1, d1));
                *(u64*)(w_s + (tx + 16*c) * ST_W + ty*8 + 2*p) = wpair;
            }
        __syncthreads();   // w visible

        // out += w @ v : w natural row-pairs, v dup'd in-register
        #pragma unroll 4
        for (int j = 0; j < 64; j++) {
            u64 wp[4];
            #pragma unroll
            for (int p = 0; p < 4; p++)
                wp[p] = *(const u64*)(w_s + j*ST_W + ty*8 + 2*p);
            u64 vp[4];
            #pragma unroll
            for (int ce = 0; ce < 4; ce++) {
                float vv = v_s[j*ST_V + tx + 16*ce];
                vp[ce] = pack2(vv, vv);
            }
            #pragma unroll
            for (int p = 0; p < 4; p++)
                #pragma unroll
                for (int ce = 0; ce < 4; ce++)
                    ffma2(out2[p][ce], wp[p], vp[ce]);
        }
        __syncthreads();   // w/v reads done before next tile overwrites
    }

    float* og = g_ao + qbase;
    #pragma unroll
    for (int p = 0; p < 4; p++)
        #pragma unroll
        for (int ce = 0; ce < 4; ce++) {
            float lo, hi;
            unpack2(out2[p][ce], lo, hi);
            int e = tx + 16*ce;
            og[(ty*8 + 2*p)     * 64 + e] = lo;
            og[(ty*8 + 2*p + 1) * 64 + e] = hi;
        }
}

// ---------------------------------------------------------------------------
// Kernel 3: output projection (R5 config).
// ---------------------------------------------------------------------------
__global__ __launch_bounds__(256) void proj_gemm(const float* __restrict__ W,
                                                 const float* __restrict__ bias,
                                                 float* __restrict__ out) {
    __shared__ __align__(16) float As[16][132];
    __shared__ __align__(16) float Bs[16][128];
    const int tid = threadIdx.x;
    const int bm = blockIdx.y * 128;
    const int bn = blockIdx.x * 128;
    const int tx = tid & 15, ty = tid >> 4;
    const int ar = tid >> 2,  ac = (tid & 3) * 4;
    const int br = tid >> 5,  bc = (tid & 31) * 4;

    u64 acc2[8][4];
    #pragma unroll
    for (int i = 0; i < 8; i++)
        #pragma unroll
        for (int p = 0; p < 4; p++) acc2[i][p] = 0ull;

    for (int kt = 0; kt < 1024; kt += 16) {
        #pragma unroll
        for (int l = 0; l < 2; l++) {
            int r = bm + ar + l * 64;
            int d = kt + ac;
            int b = r >> 11, n = r & 2047;
            int h = d >> 6,  e = d & 63;
            float4 v = *(const float4*)(g_ao + (size_t)((b * 16 + h) * 2048 + n) * 64 + e);
            int rr = ar + l * 64;
            As[ac+0][rr] = v.x; As[ac+1][rr] = v.y; As[ac+2][rr] = v.z; As[ac+3][rr] = v.w;
        }
        #pragma unroll
        for (int l = 0; l < 2; l++) {
            int r = br + l * 8;
            *(float4*)(&Bs[r][bc]) = *(const float4*)(W + (size_t)(kt + r) * 1024 + bn + bc);
        }
        __syncthreads();
        #pragma unroll
        for (int k = 0; k < 16; k++) {
            float af[8];
            *(float4*)(af)     = *(const float4*)(&As[k][ty*8]);
            *(float4*)(af + 4) = *(const float4*)(&As[k][ty*8 + 4]);
            const u64* brow = (const u64*)(&Bs[k][tx*8]);
            u64 b0 = brow[0], b1 = brow[1], b2 = brow[2], b3 = brow[3];
            #pragma unroll
            for (int i = 0; i < 8; i++) {
                u64 ap = pack2(af[i], af[i]);
                ffma2(acc2[i][0], ap, b0);
                ffma2(acc2[i][1], ap, b1);
                ffma2(acc2[i][2], ap, b2);
                ffma2(acc2[i][3], ap, b3);
            }
        }
        __syncthreads();
    }

    #pragma unroll
    for (int i = 0; i < 8; i++) {
        int r = bm + ty * 8 + i;
        #pragma unroll
        for (int p = 0; p < 4; p++) {
            int col0 = bn + tx * 8 + 2*p;
            float a0, a1;
            unpack2(acc2[i][p], a0, a1);
            *(float2*)(out + (size_t)r * 1024 + col0) =
                make_float2(a0 + bias[col0], a1 + bias[col0 + 1]);
        }
    }
}

// ---------------------------------------------------------------------------
extern "C" void kernel_launch(void* const* d_in, const int* in_sizes, int n_in,
                              void* d_out, int out_size) {
    const float* x     = (const float*)d_in[0];
    const float* w_qkv = (const float*)d_in[1];
    const float* b_qkv = (const float*)d_in[2];
    const float* w_out = (const float*)d_in[3];
    const float* b_out = (const float*)d_in[4];
    float* out = (float*)d_out;

    const int ATTN_SMEM = 117760;
    cudaFuncSetAttribute(attn_kernel, cudaFuncAttributeMaxDynamicSharedMemorySize, ATTN_SMEM);

    qkv_gemm<<<dim3(24, 32), 256>>>(x, w_qkv, b_qkv);
    attn_kernel<<<dim3(16, 32), 256, ATTN_SMEM>>>();
    proj_gemm<<<dim3(8, 32), 256>>>(w_out, b_out, out);
}